// round 14
// baseline (speedup 1.0000x reference)
#include <cuda_runtime.h>
#include <cuda_fp16.h>
#include <stdint.h>
#include <math.h>

#define B_  2
#define S_  2048
#define D_  1024
#define H_  16
#define DH_ 64
#define M_  (B_ * S_)   // 4096

// softmax scale * log2(e): applied to Q fragments inside attention (base-2 softmax)
#define QSCALE 0.18033688011112042f

// ---------------- scratch (device globals; no allocation allowed) ----------------
__device__ __half g_Xh [M_ * D_];            // LN1 output fp16 [B*S, D]
__device__ __half g_Wh [3 * D_ * D_];        // K-major fused QKV weights fp16 [3072 n][1024 k]
__device__ __half g_WOh[D_ * D_];            // K-major O weights fp16 [1024 n][1024 k]
__device__ __half g_Qh [B_ * H_ * S_ * DH_]; // [B,H,S,Dh] fp16
__device__ __half g_Kh [B_ * H_ * S_ * DH_];
__device__ __half g_Vh [B_ * H_ * S_ * DH_];
__device__ __half g_VTh[B_ * H_ * DH_ * S_]; // V transposed [B,H,Dh,S] fp16
__device__ float  g_Suf[B_ * H_ * S_ * DH_]; // suffix sums of V (fp32)
__device__ __half g_Zh [M_ * D_];            // attn z fp16, [B,S,H*Dh]
__device__ float  g_AO [M_ * D_];            // resid_mid = resid + attn_out (fp32)

// ---------------- low-level helpers ----------------
__device__ __forceinline__ uint32_t smem_u32(const void* p) {
    return (uint32_t)__cvta_generic_to_shared(p);
}
__device__ __forceinline__ void mma_f16(float c[4], const uint32_t a[4], uint32_t b0, uint32_t b1) {
    asm volatile(
        "mma.sync.aligned.m16n8k16.row.col.f32.f16.f16.f32 "
        "{%0,%1,%2,%3}, {%4,%5,%6,%7}, {%8,%9}, {%0,%1,%2,%3};"
        : "+f"(c[0]), "+f"(c[1]), "+f"(c[2]), "+f"(c[3])
        : "r"(a[0]), "r"(a[1]), "r"(a[2]), "r"(a[3]), "r"(b0), "r"(b1));
}
__device__ __forceinline__ void ldsm_x4(uint32_t& r0, uint32_t& r1, uint32_t& r2, uint32_t& r3, uint32_t addr) {
    asm volatile("ldmatrix.sync.aligned.m8n8.x4.shared.b16 {%0,%1,%2,%3}, [%4];"
                 : "=r"(r0), "=r"(r1), "=r"(r2), "=r"(r3) : "r"(addr));
}
__device__ __forceinline__ void cp_async16(uint32_t saddr, const void* gaddr) {
    asm volatile("cp.async.cg.shared.global [%0], [%1], 16;" :: "r"(saddr), "l"(gaddr) : "memory");
}
#define CP_COMMIT asm volatile("cp.async.commit_group;" ::: "memory")
#define CP_WAIT1  asm volatile("cp.async.wait_group 1;" ::: "memory")

// pack two fp32 into f16x2 (lo = x, hi = y), then 2^x elementwise
__device__ __forceinline__ uint32_t exp2_f16x2(float x, float y) {
    uint32_t c;
    asm("cvt.rn.f16x2.f32 %0, %1, %2;" : "=r"(c) : "f"(y), "f"(x));  // hi=y, lo=x
    asm("ex2.approx.f16x2 %0, %1;" : "=r"(c) : "r"(c));
    return c;
}

// ---------------- block reduction ----------------
__device__ __forceinline__ float block_reduce_sum(float v, float* sbuf) {
    int lane = threadIdx.x & 31, wid = threadIdx.x >> 5;
#pragma unroll
    for (int o = 16; o > 0; o >>= 1) v += __shfl_xor_sync(0xffffffffu, v, o);
    if (lane == 0) sbuf[wid] = v;
    __syncthreads();
    if (wid == 0) {
        float t = (lane < 8) ? sbuf[lane] : 0.f;
#pragma unroll
        for (int o = 4; o > 0; o >>= 1) t += __shfl_xor_sync(0xffffffffu, t, o);
        if (lane == 0) sbuf[0] = t;
    }
    __syncthreads();
    float r = sbuf[0];
    __syncthreads();
    return r;
}

// ---------------- weight transposes (MN-major fp32 -> K-major fp16) ----------------
__global__ void __launch_bounds__(256) transW_qkv(
    const float* __restrict__ Wq, const float* __restrict__ Wk, const float* __restrict__ Wv)
{
    __shared__ float t[32][33];
    int z = blockIdx.z, w = z >> 4, h = z & 15;
    const float* W = (w == 0) ? Wq : (w == 1) ? Wk : Wv;
    const float* src = W + (size_t)h * D_ * DH_;
    int d0 = blockIdx.x * 32, n0 = blockIdx.y * 32;
    int tx = threadIdx.x, ty = threadIdx.y;
#pragma unroll
    for (int j = 0; j < 32; j += 8)
        t[ty + j][tx] = src[(size_t)(d0 + ty + j) * DH_ + n0 + tx];
    __syncthreads();
    __half* dst = g_Wh + ((size_t)z * DH_ + n0) * D_ + d0;
#pragma unroll
    for (int j = 0; j < 32; j += 8)
        dst[(size_t)(ty + j) * D_ + tx] = __float2half_rn(t[tx][ty + j]);
}

__global__ void __launch_bounds__(256) transW_o(const float* __restrict__ WO)
{
    __shared__ float t[32][33];
    int x0 = blockIdx.x * 32, y0 = blockIdx.y * 32;
    int tx = threadIdx.x, ty = threadIdx.y;
#pragma unroll
    for (int j = 0; j < 32; j += 8)
        t[ty + j][tx] = WO[(size_t)(x0 + ty + j) * D_ + y0 + tx];
    __syncthreads();
#pragma unroll
    for (int j = 0; j < 32; j += 8)
        g_WOh[(size_t)(y0 + ty + j) * D_ + x0 + tx] = __float2half_rn(t[tx][ty + j]);
}

// ---------------- kernel 1: LN1 -> g_Xh ----------------
__global__ void __launch_bounds__(256) ln1_kernel(
    const float* __restrict__ in, const float* __restrict__ w, const float* __restrict__ b)
{
    __shared__ float sbuf[8];
    int row = blockIdx.x;
    float4 x = reinterpret_cast<const float4*>(in + (size_t)row * D_)[threadIdx.x];
    float s = x.x + x.y + x.z + x.w;
    float mean = block_reduce_sum(s, sbuf) * (1.f / D_);
    x.x -= mean; x.y -= mean; x.z -= mean; x.w -= mean;
    float ss = x.x*x.x + x.y*x.y + x.z*x.z + x.w*x.w;
    float var = block_reduce_sum(ss, sbuf) * (1.f / D_);
    float inv = rsqrtf(var + 1e-5f);
    float4 wv = reinterpret_cast<const float4*>(w)[threadIdx.x];
    float4 bv = reinterpret_cast<const float4*>(b)[threadIdx.x];
    __half2 h0 = __floats2half2_rn(x.x * inv * wv.x + bv.x, x.y * inv * wv.y + bv.y);
    __half2 h1 = __floats2half2_rn(x.z * inv * wv.z + bv.z, x.w * inv * wv.w + bv.w);
    uint2 pk;
    pk.x = *reinterpret_cast<uint32_t*>(&h0);
    pk.y = *reinterpret_cast<uint32_t*>(&h1);
    reinterpret_cast<uint2*>(g_Xh + (size_t)row * D_)[threadIdx.x] = pk;
}

// ====== fp16 GEMM: CTA 128m x 128n, 256 thr, K-chunk 64, 3-stage ring, 1 sync/iter ======
#define GST 72    // smem row stride in halves (144 B)
#define GSTAGE_H (128 * GST)                  // halves per tensor per stage
#define GEMM_SMEM (3 * 2 * GSTAGE_H * 2)      // bytes: 3 stages x 2 tensors

__device__ __forceinline__ void gemm_prefetch64(
    const __half* __restrict__ gA, const __half* __restrict__ gB,
    int m0, int n0, int k0, __half* As, __half* Bs)
{
    const int tid = threadIdx.x;
#pragma unroll
    for (int i = 0; i < 4; ++i) {
        int idx = tid + i * 256;           // 0..1023
        int r = idx >> 3, c8 = (idx & 7) * 8;
        cp_async16(smem_u32(As + r * GST + c8), gA + (size_t)(m0 + r) * D_ + k0 + c8);
        cp_async16(smem_u32(Bs + r * GST + c8), gB + (size_t)(n0 + r) * D_ + k0 + c8);
    }
}

__device__ __forceinline__ void gemm_compute64(
    const __half* As, const __half* Bs, float acc[4][4][4], int wm, int wn, int lane)
{
    const uint32_t abase = smem_u32(As);
    const uint32_t bbase = smem_u32(Bs);
    const int mi = lane >> 3, rr = lane & 7;
#pragma unroll
    for (int kk = 0; kk < 4; ++kk) {
        uint32_t a[4][4];
#pragma unroll
        for (int mt = 0; mt < 4; ++mt) {
            uint32_t addr = abase + (uint32_t)(((wm * 64 + mt * 16 + (lane & 15)) * GST + kk * 16 + (lane >> 4) * 8) * 2);
            ldsm_x4(a[mt][0], a[mt][1], a[mt][2], a[mt][3], addr);
        }
        uint32_t b0[4], b1[4];
#pragma unroll
        for (int j = 0; j < 2; ++j) {
            uint32_t addr = bbase + (uint32_t)(((wn * 32 + 16 * j + ((mi & 2) ? 8 : 0) + rr) * GST + kk * 16 + ((mi & 1) ? 8 : 0)) * 2);
            ldsm_x4(b0[2 * j], b1[2 * j], b0[2 * j + 1], b1[2 * j + 1], addr);
        }
#pragma unroll
        for (int mt = 0; mt < 4; ++mt)
#pragma unroll
            for (int nt = 0; nt < 4; ++nt)
                mma_f16(acc[mt][nt], a[mt], b0[nt], b1[nt]);
    }
}

__device__ __forceinline__ void gemm16_main(
    const __half* __restrict__ gA, const __half* __restrict__ gB,
    int m0, int n0, __half* dynsm, float acc[4][4][4], int wm, int wn, int lane)
{
#pragma unroll
    for (int mt = 0; mt < 4; ++mt)
#pragma unroll
        for (int nt = 0; nt < 4; ++nt)
#pragma unroll
            for (int r = 0; r < 4; ++r) acc[mt][nt][r] = 0.f;

    __half* A_st[3] = {dynsm,                dynsm + 2 * GSTAGE_H, dynsm + 4 * GSTAGE_H};
    __half* B_st[3] = {dynsm + GSTAGE_H,     dynsm + 3 * GSTAGE_H, dynsm + 5 * GSTAGE_H};

    gemm_prefetch64(gA, gB, m0, n0, 0,  A_st[0], B_st[0]); CP_COMMIT;
    gemm_prefetch64(gA, gB, m0, n0, 64, A_st[1], B_st[1]); CP_COMMIT;

#pragma unroll 1
    for (int c = 0; c < 16; ++c) {
        CP_WAIT1;          // per-thread: stage c's group drained (only c+1 pending)
        __syncthreads();   // publish stage c; all warps past compute(c-1) -> stage (c+2)%3 reusable
        if (c + 2 < 16)
            gemm_prefetch64(gA, gB, m0, n0, (c + 2) * 64, A_st[(c + 2) % 3], B_st[(c + 2) % 3]);
        CP_COMMIT;         // empty group near the tail keeps wait_group accounting uniform
        gemm_compute64(A_st[c % 3], B_st[c % 3], acc, wm, wn, lane);
    }
}

// QKV: grid (32 m-tiles, 24 n-tiles over fused N=3072)
__global__ void __launch_bounds__(256, 2) gemm_qkv_h(
    const float* __restrict__ bq, const float* __restrict__ bk, const float* __restrict__ bv)
{
    extern __shared__ __half dynsm[];
    const int m0 = blockIdx.x * 128, n0 = blockIdx.y * 128;
    const int tid = threadIdx.x, wid = tid >> 5, lane = tid & 31;
    const int wm = wid & 1, wn = wid >> 1;
    const int g = lane >> 2, t = lane & 3;

    float acc[4][4][4];
    gemm16_main(g_Xh, g_Wh, m0, n0, dynsm, acc, wm, wn, lane);

    const int wsel = n0 >> 10;
    __half* Out       = (wsel == 0) ? g_Qh : (wsel == 1) ? g_Kh : g_Vh;
    const float* bias = (wsel == 0) ? bq : (wsel == 1) ? bk : bv;

#pragma unroll
    for (int nt = 0; nt < 4; ++nt) {
        int cw = (n0 & 1023) + wn * 32 + nt * 8 + 2 * t;     // col within weight
        int h = cw >> 6, dh = cw & 63;
        float b0 = bias[cw], b1 = bias[cw + 1];
#pragma unroll
        for (int mt = 0; mt < 4; ++mt) {
#pragma unroll
            for (int hf = 0; hf < 2; ++hf) {
                int m = m0 + wm * 64 + mt * 16 + g + 8 * hf;
                int bb = m >> 11, ss = m & (S_ - 1);
                __half2 hv = __floats2half2_rn(acc[mt][nt][2 * hf] + b0, acc[mt][nt][2 * hf + 1] + b1);
                *reinterpret_cast<__half2*>(Out + ((size_t)((bb * H_ + h) * S_ + ss)) * DH_ + dh) = hv;
            }
        }
    }
}

// O-proj: grid (32, 8). Epilogue fuses resid add: g_AO = resid + attn_out (resid_mid).
__global__ void __launch_bounds__(256, 2) gemm_o_h(
    const float* __restrict__ bO, const float* __restrict__ resid)
{
    extern __shared__ __half dynsm[];
    const int m0 = blockIdx.x * 128, n0 = blockIdx.y * 128;
    const int tid = threadIdx.x, wid = tid >> 5, lane = tid & 31;
    const int wm = wid & 1, wn = wid >> 1;
    const int g = lane >> 2, t = lane & 3;

    float acc[4][4][4];
    gemm16_main(g_Zh, g_WOh, m0, n0, dynsm, acc, wm, wn, lane);

#pragma unroll
    for (int nt = 0; nt < 4; ++nt) {
        int col = n0 + wn * 32 + nt * 8 + 2 * t;
        float b0 = bO[col], b1 = bO[col + 1];
#pragma unroll
        for (int mt = 0; mt < 4; ++mt) {
#pragma unroll
            for (int hf = 0; hf < 2; ++hf) {
                int m = m0 + wm * 64 + mt * 16 + g + 8 * hf;
                float2 rp = *reinterpret_cast<const float2*>(resid + (size_t)m * D_ + col);
                float2 o;
                o.x = acc[mt][nt][2 * hf] + b0 + rp.x;
                o.y = acc[mt][nt][2 * hf + 1] + b1 + rp.y;
                *reinterpret_cast<float2*>(g_AO + (size_t)m * D_ + col) = o;
            }
        }
    }
}

// ---------------- kernel 3: suffix sums of V + V^T production ----------------
__global__ void __launch_bounds__(1024) suffix_kernel()
{
    int bh = blockIdx.x;
    int d  = threadIdx.x & 63;
    int seg = threadIdx.x >> 6;  // 0..15
    const __half* v = g_Vh + (size_t)bh * S_ * DH_;
    float* suf = g_Suf + (size_t)bh * S_ * DH_;
    __half* vtrow = g_VTh + ((size_t)bh * DH_ + d) * S_;

    int s_begin = seg * 128, s_end = s_begin + 128;
    float ssum = 0.f;
    for (int s = s_begin; s < s_end; ++s) ssum += __half2float(v[s * DH_ + d]);

    __shared__ float segsum[16][64];
    segsum[seg][d] = ssum;
    __syncthreads();
    float acc = 0.f;
    for (int tt = seg + 1; tt < 16; ++tt) acc += segsum[tt][d];

    for (int s0 = s_end - 8; s0 >= s_begin; s0 -= 8) {
        __half hv[8];
        float vv[8];
#pragma unroll
        for (int tt = 0; tt < 8; ++tt) {
            hv[tt] = v[(s0 + tt) * DH_ + d];
            vv[tt] = __half2float(hv[tt]);
        }
        *reinterpret_cast<uint4*>(vtrow + s0) = *reinterpret_cast<uint4*>(hv);
#pragma unroll
        for (int tt = 7; tt >= 0; --tt) { suf[(s0 + tt) * DH_ + d] = acc; acc += vv[tt]; }
    }
}

// ------ kernel 4: flash attention (fp16 MMA, pipelined exp/PV, base-2 softmax) ------
#define AKST 72                               // K/V^T smem row stride in halves (144 B)
#define AKSTAGE_H (64 * AKST)                 // halves per tensor per stage
#define ATTN_SMEM (3 * 2 * AKSTAGE_H * 2)     // bytes (55296)

__device__ __forceinline__ void attn_prefetch(
    const __half* __restrict__ Kp, const __half* __restrict__ VTp,
    int kt, __half* Ks, __half* Vt)
{
    const int tid = threadIdx.x;
#pragma unroll
    for (int i = 0; i < 2; ++i) {
        int idx = tid + i * 256;
        int r = idx >> 3, c8 = (idx & 7) * 8;
        cp_async16(smem_u32(Ks + r * AKST + c8), Kp + (size_t)(kt * 64 + r) * DH_ + c8);
        cp_async16(smem_u32(Vt + r * AKST + c8), VTp + (size_t)r * S_ + kt * 64 + c8);
    }
}

__global__ void __launch_bounds__(256, 2) attn_kernel()
{
    extern __shared__ __half asm_[];
    __half* K_st[3] = {asm_,                 asm_ + 2 * AKSTAGE_H, asm_ + 4 * AKSTAGE_H};
    __half* V_st[3] = {asm_ + AKSTAGE_H,     asm_ + 3 * AKSTAGE_H, asm_ + 5 * AKSTAGE_H};

    const int qt = 15 - blockIdx.x;    // heavy tiles first
    const int h = blockIdx.y, b = blockIdx.z;
    const int bh = b * H_ + h;
    const __half* Qp  = g_Qh  + (size_t)bh * S_ * DH_;
    const __half* Kp  = g_Kh  + (size_t)bh * S_ * DH_;
    const __half* VTp = g_VTh + (size_t)bh * DH_ * S_;

    const int tid = threadIdx.x;
    const int w = tid >> 5, lane = tid & 31;
    const int g = lane >> 2, t = lane & 3;
    const int mi = lane >> 3, rr = lane & 7;
    const int q0 = qt * 128;
    const int r0 = 16 * w + g;
    const int q_g0 = q0 + r0, q_g1 = q_g0 + 8;

    // Q fragments (gmem direct; rows are warp-private), scaled by QSCALE via HMUL2
    const __half2 qsc = __float2half2_rn(QSCALE);
    uint32_t qa[4][4];
#pragma unroll
    for (int kk = 0; kk < 4; ++kk) {
        qa[kk][0] = *reinterpret_cast<const uint32_t*>(Qp + (size_t)q_g0 * DH_ + 16 * kk + 2 * t);
        qa[kk][1] = *reinterpret_cast<const uint32_t*>(Qp + (size_t)q_g1 * DH_ + 16 * kk + 2 * t);
        qa[kk][2] = *reinterpret_cast<const uint32_t*>(Qp + (size_t)q_g0 * DH_ + 16 * kk + 2 * t + 8);
        qa[kk][3] = *reinterpret_cast<const uint32_t*>(Qp + (size_t)q_g1 * DH_ + 16 * kk + 2 * t + 8);
#pragma unroll
        for (int r = 0; r < 4; ++r) {
            __half2 hq = *reinterpret_cast<__half2*>(&qa[kk][r]);
            hq = __hmul2(hq, qsc);
            qa[kk][r] = *reinterpret_cast<uint32_t*>(&hq);
        }
    }

    float z[8][4];
#pragma unroll
    for (int nt = 0; nt < 8; ++nt)
#pragma unroll
        for (int r = 0; r < 4; ++r) z[nt][r] = 0.f;
    float l0 = 0.f, l1 = 0.f;

    const int NC = 2 * qt + 2;   // always >= 2

    attn_prefetch(Kp, VTp, 0, K_st[0], V_st[0]); CP_COMMIT;
    attn_prefetch(Kp, VTp, 1, K_st[1], V_st[1]); CP_COMMIT;

#pragma unroll 1
    for (int kt = 0; kt < NC; ++kt) {
        CP_WAIT1;          // stage kt drained (per-thread)
        __syncthreads();   // publish stage kt; stage (kt+2)%3 free of readers
        if (kt + 2 < NC)
            attn_prefetch(Kp, VTp, kt + 2, K_st[(kt + 2) % 3], V_st[(kt + 2) % 3]);
        CP_COMMIT;

        const uint32_t kbase = smem_u32(K_st[kt % 3]);
        const uint32_t vbase = smem_u32(V_st[kt % 3]);

        // ---- S = Q @ K^T  (base-2 domain; scale folded into Q frags) ----
        float sv[8][4];
#pragma unroll
        for (int nt = 0; nt < 8; ++nt)
#pragma unroll
            for (int r = 0; r < 4; ++r) sv[nt][r] = 0.f;
#pragma unroll
        for (int kk = 0; kk < 4; ++kk) {
            uint32_t kb0[8], kb1[8];
#pragma unroll
            for (int j = 0; j < 4; ++j) {
                uint32_t addr = kbase + (uint32_t)(((16 * j + ((mi & 2) ? 8 : 0) + rr) * AKST + kk * 16 + ((mi & 1) ? 8 : 0)) * 2);
                ldsm_x4(kb0[2 * j], kb1[2 * j], kb0[2 * j + 1], kb1[2 * j + 1], addr);
            }
#pragma unroll
            for (int nt = 0; nt < 8; ++nt)
                mma_f16(sv[nt], qa[kk], kb0[nt], kb1[nt]);
        }

        // ---- causal mask on diagonal tiles ----
        if (kt >= 2 * qt) {
#pragma unroll
            for (int nt = 0; nt < 8; ++nt) {
                int p = kt * 64 + 8 * nt + 2 * t;
                if (p     > q_g0) sv[nt][0] = -1e30f;
                if (p + 1 > q_g0) sv[nt][1] = -1e30f;
                if (p     > q_g1) sv[nt][2] = -1e30f;
                if (p + 1 > q_g1) sv[nt][3] = -1e30f;
            }
        }

        // ---- pipelined exp/PV: PV(kk2) only needs exp of score pair kk2, so the
        //      MUFU work for pair kk2+1 overlaps the V-ldsm + tensor MMAs of pair kk2 ----
        __half2 la0 = __float2half2_rn(0.f), la1 = __float2half2_rn(0.f);
        uint32_t pa_cur[4];
        // pair 0: pa = {ph0[0], ph1[0], ph0[1], ph1[1]}
        pa_cur[0] = exp2_f16x2(sv[0][0], sv[0][1]);
        pa_cur[1] = exp2_f16x2(sv[0][2], sv[0][3]);
        pa_cur[2] = exp2_f16x2(sv[1][0], sv[1][1]);
        pa_cur[3] = exp2_f16x2(sv[1][2], sv[1][3]);
        la0 = __hadd2(la0, *reinterpret_cast<__half2*>(&pa_cur[0]));
        la1 = __hadd2(la1, *reinterpret_cast<__half2*>(&pa_cur[1]));
        la0 = __hadd2(la0, *reinterpret_cast<__half2*>(&pa_cur[2]));
        la1 = __hadd2(la1, *reinterpret_cast<__half2*>(&pa_cur[3]));

#pragma unroll
        for (int kk2 = 0; kk2 < 4; ++kk2) {
            // V fragments for this pair (LDS latency overlapped by the exp below)
            uint32_t vb0[8], vb1[8];
#pragma unroll
            for (int j = 0; j < 4; ++j) {
                uint32_t addr = vbase + (uint32_t)(((16 * j + ((mi & 2) ? 8 : 0) + rr) * AKST + kk2 * 16 + ((mi & 1) ? 8 : 0)) * 2);
                ldsm_x4(vb0[2 * j], vb1[2 * j], vb0[2 * j + 1], vb1[2 * j + 1], addr);
            }
            // exp for the NEXT pair (independent of this pair's MMAs)
            uint32_t pa_nxt[4];
            if (kk2 < 3) {
                int p0 = 2 * kk2 + 2, p1 = 2 * kk2 + 3;
                pa_nxt[0] = exp2_f16x2(sv[p0][0], sv[p0][1]);
                pa_nxt[1] = exp2_f16x2(sv[p0][2], sv[p0][3]);
                pa_nxt[2] = exp2_f16x2(sv[p1][0], sv[p1][1]);
                pa_nxt[3] = exp2_f16x2(sv[p1][2], sv[p1][3]);
                la0 = __hadd2(la0, *reinterpret_cast<__half2*>(&pa_nxt[0]));
                la1 = __hadd2(la1, *reinterpret_cast<__half2*>(&pa_nxt[1]));
                la0 = __hadd2(la0, *reinterpret_cast<__half2*>(&pa_nxt[2]));
                la1 = __hadd2(la1, *reinterpret_cast<__half2*>(&pa_nxt[3]));
            }
            // PV MMAs for the current pair
#pragma unroll
            for (int nt = 0; nt < 8; ++nt)
                mma_f16(z[nt], pa_cur, vb0[nt], vb1[nt]);
            if (kk2 < 3) {
                pa_cur[0] = pa_nxt[0]; pa_cur[1] = pa_nxt[1];
                pa_cur[2] = pa_nxt[2]; pa_cur[3] = pa_nxt[3];
            }
        }

        {
            float2 f0 = __half22float2(la0);
            float2 f1 = __half22float2(la1);
            l0 += f0.x + f0.y;
            l1 += f1.x + f1.y;
        }
    }

    // reduce denominators across the 4 t-lanes of each row group
#pragma unroll
    for (int o = 1; o < 4; o <<= 1) {
        l0 += __shfl_xor_sync(0xffffffffu, l0, o);
        l1 += __shfl_xor_sync(0xffffffffu, l1, o);
    }
    float inv0 = 1.f / (l0 + (float)(S_ - 1 - q_g0));
    float inv1 = 1.f / (l1 + (float)(S_ - 1 - q_g1));
    const float* suf0 = g_Suf + ((size_t)bh * S_ + q_g0) * DH_;
    const float* suf1 = g_Suf + ((size_t)bh * S_ + q_g1) * DH_;
    __half* zr0 = g_Zh + ((size_t)(b * S_ + q_g0) * H_ + h) * DH_;
    __half* zr1 = g_Zh + ((size_t)(b * S_ + q_g1) * H_ + h) * DH_;
#pragma unroll
    for (int nt = 0; nt < 8; ++nt) {
        int c = 8 * nt + 2 * t;
        float2 sA = *reinterpret_cast<const float2*>(suf0 + c);
        float2 sB = *reinterpret_cast<const float2*>(suf1 + c);
        *reinterpret_cast<__half2*>(zr0 + c) =
            __floats2half2_rn((z[nt][0] + sA.x) * inv0, (z[nt][1] + sA.y) * inv0);
        *reinterpret_cast<__half2*>(zr1 + c) =
            __floats2half2_rn((z[nt][2] + sB.x) * inv1, (z[nt][3] + sB.y) * inv1);
    }
}

// ---------------- kernel 6: LN2 on resid_mid (g_AO) + residual ----------------
__global__ void __launch_bounds__(256) final_kernel(
    const float* __restrict__ w, const float* __restrict__ b, float* __restrict__ out)
{
    __shared__ float sbuf[8];
    int row = blockIdx.x;
    float4 rm = reinterpret_cast<const float4*>(g_AO + (size_t)row * D_)[threadIdx.x];
    float s = rm.x + rm.y + rm.z + rm.w;
    float mean = block_reduce_sum(s, sbuf) * (1.f / D_);
    float4 c;
    c.x = rm.x - mean; c.y = rm.y - mean; c.z = rm.z - mean; c.w = rm.w - mean;
    float ss = c.x*c.x + c.y*c.y + c.z*c.z + c.w*c.w;
    float var = block_reduce_sum(ss, sbuf) * (1.f / D_);
    float inv = rsqrtf(var + 1e-5f);
    float4 wv = reinterpret_cast<const float4*>(w)[threadIdx.x];
    float4 bv = reinterpret_cast<const float4*>(b)[threadIdx.x];
    float4 o;
    o.x = rm.x + (c.x * inv * wv.x + bv.x);
    o.y = rm.y + (c.y * inv * wv.y + bv.y);
    o.z = rm.z + (c.z * inv * wv.z + bv.z);
    o.w = rm.w + (c.w * inv * wv.w + bv.w);
    reinterpret_cast<float4*>(out + (size_t)row * D_)[threadIdx.x] = o;
}

// ---------------- launch ----------------
extern "C" void kernel_launch(void* const* d_in, const int* in_sizes, int n_in,
                              void* d_out, int out_size)
{
    const float* resid = (const float*)d_in[0];
    const float* Wq    = (const float*)d_in[1];
    const float* bq    = (const float*)d_in[2];
    const float* Wk    = (const float*)d_in[3];
    const float* bk    = (const float*)d_in[4];
    const float* Wv    = (const float*)d_in[5];
    const float* bv    = (const float*)d_in[6];
    const float* Wo    = (const float*)d_in[7];
    const float* bo    = (const float*)d_in[8];
    const float* ln1w  = (const float*)d_in[9];
    const float* ln1b  = (const float*)d_in[10];
    const float* ln2w  = (const float*)d_in[11];
    const float* ln2b  = (const float*)d_in[12];
    float* out = (float*)d_out;

    cudaFuncSetAttribute(gemm_qkv_h,  cudaFuncAttributeMaxDynamicSharedMemorySize, GEMM_SMEM);
    cudaFuncSetAttribute(gemm_o_h,    cudaFuncAttributeMaxDynamicSharedMemorySize, GEMM_SMEM);
    cudaFuncSetAttribute(attn_kernel, cudaFuncAttributeMaxDynamicSharedMemorySize, ATTN_SMEM);

    transW_qkv<<<dim3(32, 2, 48), dim3(32, 8)>>>(Wq, Wk, Wv);
    transW_o<<<dim3(32, 32), dim3(32, 8)>>>(Wo);
    ln1_kernel<<<M_, 256>>>(resid, ln1w, ln1b);
    gemm_qkv_h<<<dim3(M_ / 128, 24), 256, GEMM_SMEM>>>(bq, bk, bv);
    suffix_kernel<<<B_ * H_, 1024>>>();
    attn_kernel<<<dim3(16, H_, B_), 256, ATTN_SMEM>>>();
    gemm_o_h<<<dim3(M_ / 128, 8), 256, GEMM_SMEM>>>(bo, resid);
    final_kernel<<<M_, 256>>>(ln2w, ln2b, out);
}

// round 15
// speedup vs baseline: 1.0150x; 1.0150x over previous
#include <cuda_runtime.h>
#include <cuda_fp16.h>
#include <stdint.h>
#include <math.h>

#define B_  2
#define S_  2048
#define D_  1024
#define H_  16
#define DH_ 64
#define M_  (B_ * S_)   // 4096

// softmax scale * log2(e): applied to Q fragments inside attention (base-2 softmax)
#define QSCALE 0.18033688011112042f

// ---------------- scratch (device globals; no allocation allowed) ----------------
__device__ __half g_Xh [M_ * D_];            // LN1 output fp16 [B*S, D]
__device__ __half g_Wh [3 * D_ * D_];        // K-major fused QKV weights fp16 [3072 n][1024 k]
__device__ __half g_WOh[D_ * D_];            // K-major O weights fp16 [1024 n][1024 k]
__device__ __half g_Qh [B_ * H_ * S_ * DH_]; // [B,H,S,Dh] fp16
__device__ __half g_Kh [B_ * H_ * S_ * DH_];
__device__ __half g_Vh [B_ * H_ * S_ * DH_];
__device__ __half g_VTh[B_ * H_ * DH_ * S_]; // V transposed [B,H,Dh,S] fp16
__device__ float  g_Suf[B_ * H_ * S_ * DH_]; // suffix sums of V (fp32)
__device__ __half g_Zh [M_ * D_];            // attn z fp16, [B,S,H*Dh]
__device__ float  g_AO [M_ * D_];            // resid_mid = resid + attn_out (fp32)

// ---------------- low-level helpers ----------------
__device__ __forceinline__ uint32_t smem_u32(const void* p) {
    return (uint32_t)__cvta_generic_to_shared(p);
}
__device__ __forceinline__ void mma_f16(float c[4], const uint32_t a[4], uint32_t b0, uint32_t b1) {
    asm volatile(
        "mma.sync.aligned.m16n8k16.row.col.f32.f16.f16.f32 "
        "{%0,%1,%2,%3}, {%4,%5,%6,%7}, {%8,%9}, {%0,%1,%2,%3};"
        : "+f"(c[0]), "+f"(c[1]), "+f"(c[2]), "+f"(c[3])
        : "r"(a[0]), "r"(a[1]), "r"(a[2]), "r"(a[3]), "r"(b0), "r"(b1));
}
__device__ __forceinline__ void ldsm_x4(uint32_t& r0, uint32_t& r1, uint32_t& r2, uint32_t& r3, uint32_t addr) {
    asm volatile("ldmatrix.sync.aligned.m8n8.x4.shared.b16 {%0,%1,%2,%3}, [%4];"
                 : "=r"(r0), "=r"(r1), "=r"(r2), "=r"(r3) : "r"(addr));
}
__device__ __forceinline__ void cp_async16(uint32_t saddr, const void* gaddr) {
    asm volatile("cp.async.cg.shared.global [%0], [%1], 16;" :: "r"(saddr), "l"(gaddr) : "memory");
}
#define CP_COMMIT asm volatile("cp.async.commit_group;" ::: "memory")
#define CP_WAIT1  asm volatile("cp.async.wait_group 1;" ::: "memory")

// pack two fp32 into f16x2 (lo = x, hi = y), then 2^x elementwise
__device__ __forceinline__ uint32_t exp2_f16x2(float x, float y) {
    uint32_t c;
    asm("cvt.rn.f16x2.f32 %0, %1, %2;" : "=r"(c) : "f"(y), "f"(x));  // hi=y, lo=x
    asm("ex2.approx.f16x2 %0, %1;" : "=r"(c) : "r"(c));
    return c;
}

// ---------------- block reduction ----------------
__device__ __forceinline__ float block_reduce_sum(float v, float* sbuf) {
    int lane = threadIdx.x & 31, wid = threadIdx.x >> 5;
#pragma unroll
    for (int o = 16; o > 0; o >>= 1) v += __shfl_xor_sync(0xffffffffu, v, o);
    if (lane == 0) sbuf[wid] = v;
    __syncthreads();
    if (wid == 0) {
        float t = (lane < 8) ? sbuf[lane] : 0.f;
#pragma unroll
        for (int o = 4; o > 0; o >>= 1) t += __shfl_xor_sync(0xffffffffu, t, o);
        if (lane == 0) sbuf[0] = t;
    }
    __syncthreads();
    float r = sbuf[0];
    __syncthreads();
    return r;
}

// ======= kernel 1 (fused prep): weight transposes + LN1, one launch =======
// blocks [0,3072):  transW_qkv   (32 d-tiles x 2 n-tiles x 48 (w,h))
// blocks [3072,4096): transW_o   (32 x 32 tiles)
// blocks [4096,8192): LN1 rows
__global__ void __launch_bounds__(256) prep_kernel(
    const float* __restrict__ Wq, const float* __restrict__ Wk, const float* __restrict__ Wv,
    const float* __restrict__ WO,
    const float* __restrict__ in, const float* __restrict__ lw, const float* __restrict__ lb)
{
    __shared__ float tbuf[32][33];
    const int bid = blockIdx.x;
    const int tx = threadIdx.x & 31, ty = threadIdx.x >> 5;

    if (bid < 3072) {
        // ---- QKV weight transpose: W[h][d][n] -> g_Wh[(w*16+h)*64+n][d] (fp16) ----
        int z = bid >> 6, rem = bid & 63;
        int x = rem & 31, y = rem >> 5;
        int w = z >> 4, h = z & 15;
        const float* W = (w == 0) ? Wq : (w == 1) ? Wk : Wv;
        const float* src = W + (size_t)h * D_ * DH_;
        int d0 = x * 32, n0 = y * 32;
#pragma unroll
        for (int j = 0; j < 32; j += 8)
            tbuf[ty + j][tx] = src[(size_t)(d0 + ty + j) * DH_ + n0 + tx];
        __syncthreads();
        __half* dst = g_Wh + ((size_t)z * DH_ + n0) * D_ + d0;
#pragma unroll
        for (int j = 0; j < 32; j += 8)
            dst[(size_t)(ty + j) * D_ + tx] = __float2half_rn(tbuf[tx][ty + j]);
    } else if (bid < 4096) {
        // ---- O weight transpose: W_O[hk][d] -> g_WOh[d][hk] (fp16) ----
        int obid = bid - 3072;
        int x0 = (obid & 31) * 32, y0 = (obid >> 5) * 32;
#pragma unroll
        for (int j = 0; j < 32; j += 8)
            tbuf[ty + j][tx] = WO[(size_t)(x0 + ty + j) * D_ + y0 + tx];
        __syncthreads();
#pragma unroll
        for (int j = 0; j < 32; j += 8)
            g_WOh[(size_t)(y0 + ty + j) * D_ + x0 + tx] = __float2half_rn(tbuf[tx][ty + j]);
    } else {
        // ---- LN1 row -> g_Xh (fp16) ----
        float* sbuf = &tbuf[0][0];
        int row = bid - 4096;
        float4 x = reinterpret_cast<const float4*>(in + (size_t)row * D_)[threadIdx.x];
        float s = x.x + x.y + x.z + x.w;
        float mean = block_reduce_sum(s, sbuf) * (1.f / D_);
        x.x -= mean; x.y -= mean; x.z -= mean; x.w -= mean;
        float ss = x.x*x.x + x.y*x.y + x.z*x.z + x.w*x.w;
        float var = block_reduce_sum(ss, sbuf) * (1.f / D_);
        float inv = rsqrtf(var + 1e-5f);
        float4 wv = reinterpret_cast<const float4*>(lw)[threadIdx.x];
        float4 bv = reinterpret_cast<const float4*>(lb)[threadIdx.x];
        __half2 h0 = __floats2half2_rn(x.x * inv * wv.x + bv.x, x.y * inv * wv.y + bv.y);
        __half2 h1 = __floats2half2_rn(x.z * inv * wv.z + bv.z, x.w * inv * wv.w + bv.w);
        uint2 pk;
        pk.x = *reinterpret_cast<uint32_t*>(&h0);
        pk.y = *reinterpret_cast<uint32_t*>(&h1);
        reinterpret_cast<uint2*>(g_Xh + (size_t)row * D_)[threadIdx.x] = pk;
    }
}

// ====== fp16 GEMM: CTA 128m x 128n, 256 thr, K-chunk 64, 3-stage ring, 1 sync/iter ======
#define GST 72    // smem row stride in halves (144 B)
#define GSTAGE_H (128 * GST)                  // halves per tensor per stage
#define GEMM_SMEM (3 * 2 * GSTAGE_H * 2)      // bytes: 3 stages x 2 tensors

__device__ __forceinline__ void gemm_prefetch64(
    const __half* __restrict__ gA, const __half* __restrict__ gB,
    int m0, int n0, int k0, __half* As, __half* Bs)
{
    const int tid = threadIdx.x;
#pragma unroll
    for (int i = 0; i < 4; ++i) {
        int idx = tid + i * 256;           // 0..1023
        int r = idx >> 3, c8 = (idx & 7) * 8;
        cp_async16(smem_u32(As + r * GST + c8), gA + (size_t)(m0 + r) * D_ + k0 + c8);
        cp_async16(smem_u32(Bs + r * GST + c8), gB + (size_t)(n0 + r) * D_ + k0 + c8);
    }
}

__device__ __forceinline__ void gemm_compute64(
    const __half* As, const __half* Bs, float acc[4][4][4], int wm, int wn, int lane)
{
    const uint32_t abase = smem_u32(As);
    const uint32_t bbase = smem_u32(Bs);
    const int mi = lane >> 3, rr = lane & 7;
#pragma unroll
    for (int kk = 0; kk < 4; ++kk) {
        uint32_t a[4][4];
#pragma unroll
        for (int mt = 0; mt < 4; ++mt) {
            uint32_t addr = abase + (uint32_t)(((wm * 64 + mt * 16 + (lane & 15)) * GST + kk * 16 + (lane >> 4) * 8) * 2);
            ldsm_x4(a[mt][0], a[mt][1], a[mt][2], a[mt][3], addr);
        }
        uint32_t b0[4], b1[4];
#pragma unroll
        for (int j = 0; j < 2; ++j) {
            uint32_t addr = bbase + (uint32_t)(((wn * 32 + 16 * j + ((mi & 2) ? 8 : 0) + rr) * GST + kk * 16 + ((mi & 1) ? 8 : 0)) * 2);
            ldsm_x4(b0[2 * j], b1[2 * j], b0[2 * j + 1], b1[2 * j + 1], addr);
        }
#pragma unroll
        for (int mt = 0; mt < 4; ++mt)
#pragma unroll
            for (int nt = 0; nt < 4; ++nt)
                mma_f16(acc[mt][nt], a[mt], b0[nt], b1[nt]);
    }
}

__device__ __forceinline__ void gemm16_main(
    const __half* __restrict__ gA, const __half* __restrict__ gB,
    int m0, int n0, __half* dynsm, float acc[4][4][4], int wm, int wn, int lane)
{
#pragma unroll
    for (int mt = 0; mt < 4; ++mt)
#pragma unroll
        for (int nt = 0; nt < 4; ++nt)
#pragma unroll
            for (int r = 0; r < 4; ++r) acc[mt][nt][r] = 0.f;

    __half* A_st[3] = {dynsm,                dynsm + 2 * GSTAGE_H, dynsm + 4 * GSTAGE_H};
    __half* B_st[3] = {dynsm + GSTAGE_H,     dynsm + 3 * GSTAGE_H, dynsm + 5 * GSTAGE_H};

    gemm_prefetch64(gA, gB, m0, n0, 0,  A_st[0], B_st[0]); CP_COMMIT;
    gemm_prefetch64(gA, gB, m0, n0, 64, A_st[1], B_st[1]); CP_COMMIT;

#pragma unroll 1
    for (int c = 0; c < 16; ++c) {
        CP_WAIT1;          // per-thread: stage c's group drained (only c+1 pending)
        __syncthreads();   // publish stage c; all warps past compute(c-1) -> stage (c+2)%3 reusable
        if (c + 2 < 16)
            gemm_prefetch64(gA, gB, m0, n0, (c + 2) * 64, A_st[(c + 2) % 3], B_st[(c + 2) % 3]);
        CP_COMMIT;         // empty group near the tail keeps wait_group accounting uniform
        gemm_compute64(A_st[c % 3], B_st[c % 3], acc, wm, wn, lane);
    }
}

// QKV: grid (32 m-tiles, 24 n-tiles over fused N=3072)
__global__ void __launch_bounds__(256, 2) gemm_qkv_h(
    const float* __restrict__ bq, const float* __restrict__ bk, const float* __restrict__ bv)
{
    extern __shared__ __half dynsm[];
    const int m0 = blockIdx.x * 128, n0 = blockIdx.y * 128;
    const int tid = threadIdx.x, wid = tid >> 5, lane = tid & 31;
    const int wm = wid & 1, wn = wid >> 1;
    const int g = lane >> 2, t = lane & 3;

    float acc[4][4][4];
    gemm16_main(g_Xh, g_Wh, m0, n0, dynsm, acc, wm, wn, lane);

    const int wsel = n0 >> 10;
    __half* Out       = (wsel == 0) ? g_Qh : (wsel == 1) ? g_Kh : g_Vh;
    const float* bias = (wsel == 0) ? bq : (wsel == 1) ? bk : bv;

#pragma unroll
    for (int nt = 0; nt < 4; ++nt) {
        int cw = (n0 & 1023) + wn * 32 + nt * 8 + 2 * t;     // col within weight
        int h = cw >> 6, dh = cw & 63;
        float b0 = bias[cw], b1 = bias[cw + 1];
#pragma unroll
        for (int mt = 0; mt < 4; ++mt) {
#pragma unroll
            for (int hf = 0; hf < 2; ++hf) {
                int m = m0 + wm * 64 + mt * 16 + g + 8 * hf;
                int bb = m >> 11, ss = m & (S_ - 1);
                __half2 hv = __floats2half2_rn(acc[mt][nt][2 * hf] + b0, acc[mt][nt][2 * hf + 1] + b1);
                *reinterpret_cast<__half2*>(Out + ((size_t)((bb * H_ + h) * S_ + ss)) * DH_ + dh) = hv;
            }
        }
    }
}

// O-proj: grid (32, 8). Epilogue fuses resid add: g_AO = resid + attn_out (resid_mid).
__global__ void __launch_bounds__(256, 2) gemm_o_h(
    const float* __restrict__ bO, const float* __restrict__ resid)
{
    extern __shared__ __half dynsm[];
    const int m0 = blockIdx.x * 128, n0 = blockIdx.y * 128;
    const int tid = threadIdx.x, wid = tid >> 5, lane = tid & 31;
    const int wm = wid & 1, wn = wid >> 1;
    const int g = lane >> 2, t = lane & 3;

    float acc[4][4][4];
    gemm16_main(g_Zh, g_WOh, m0, n0, dynsm, acc, wm, wn, lane);

#pragma unroll
    for (int nt = 0; nt < 4; ++nt) {
        int col = n0 + wn * 32 + nt * 8 + 2 * t;
        float b0 = bO[col], b1 = bO[col + 1];
#pragma unroll
        for (int mt = 0; mt < 4; ++mt) {
#pragma unroll
            for (int hf = 0; hf < 2; ++hf) {
                int m = m0 + wm * 64 + mt * 16 + g + 8 * hf;
                float2 rp = *reinterpret_cast<const float2*>(resid + (size_t)m * D_ + col);
                float2 o;
                o.x = acc[mt][nt][2 * hf] + b0 + rp.x;
                o.y = acc[mt][nt][2 * hf + 1] + b1 + rp.y;
                *reinterpret_cast<float2*>(g_AO + (size_t)m * D_ + col) = o;
            }
        }
    }
}

// ---------------- kernel 3: suffix sums of V + V^T production ----------------
__global__ void __launch_bounds__(1024) suffix_kernel()
{
    int bh = blockIdx.x;
    int d  = threadIdx.x & 63;
    int seg = threadIdx.x >> 6;  // 0..15
    const __half* v = g_Vh + (size_t)bh * S_ * DH_;
    float* suf = g_Suf + (size_t)bh * S_ * DH_;
    __half* vtrow = g_VTh + ((size_t)bh * DH_ + d) * S_;

    int s_begin = seg * 128, s_end = s_begin + 128;
    float ssum = 0.f;
    for (int s = s_begin; s < s_end; ++s) ssum += __half2float(v[s * DH_ + d]);

    __shared__ float segsum[16][64];
    segsum[seg][d] = ssum;
    __syncthreads();
    float acc = 0.f;
    for (int tt = seg + 1; tt < 16; ++tt) acc += segsum[tt][d];

    for (int s0 = s_end - 8; s0 >= s_begin; s0 -= 8) {
        __half hv[8];
        float vv[8];
#pragma unroll
        for (int tt = 0; tt < 8; ++tt) {
            hv[tt] = v[(s0 + tt) * DH_ + d];
            vv[tt] = __half2float(hv[tt]);
        }
        *reinterpret_cast<uint4*>(vtrow + s0) = *reinterpret_cast<uint4*>(hv);
#pragma unroll
        for (int tt = 7; tt >= 0; --tt) { suf[(s0 + tt) * DH_ + d] = acc; acc += vv[tt]; }
    }
}

// ------ kernel 4: flash attention (fp16 MMA, base-2 softmax via ex2.f16x2) ------
#define AKST 72                               // K/V^T smem row stride in halves (144 B)
#define AKSTAGE_H (64 * AKST)                 // halves per tensor per stage
#define ATTN_SMEM (3 * 2 * AKSTAGE_H * 2)     // bytes (55296)

__device__ __forceinline__ void attn_prefetch(
    const __half* __restrict__ Kp, const __half* __restrict__ VTp,
    int kt, __half* Ks, __half* Vt)
{
    const int tid = threadIdx.x;
#pragma unroll
    for (int i = 0; i < 2; ++i) {
        int idx = tid + i * 256;
        int r = idx >> 3, c8 = (idx & 7) * 8;
        cp_async16(smem_u32(Ks + r * AKST + c8), Kp + (size_t)(kt * 64 + r) * DH_ + c8);
        cp_async16(smem_u32(Vt + r * AKST + c8), VTp + (size_t)r * S_ + kt * 64 + c8);
    }
}

__global__ void __launch_bounds__(256, 2) attn_kernel()
{
    extern __shared__ __half asm_[];
    __half* K_st[3] = {asm_,                 asm_ + 2 * AKSTAGE_H, asm_ + 4 * AKSTAGE_H};
    __half* V_st[3] = {asm_ + AKSTAGE_H,     asm_ + 3 * AKSTAGE_H, asm_ + 5 * AKSTAGE_H};

    const int qt = 15 - blockIdx.x;    // heavy tiles first
    const int h = blockIdx.y, b = blockIdx.z;
    const int bh = b * H_ + h;
    const __half* Qp  = g_Qh  + (size_t)bh * S_ * DH_;
    const __half* Kp  = g_Kh  + (size_t)bh * S_ * DH_;
    const __half* VTp = g_VTh + (size_t)bh * DH_ * S_;

    const int tid = threadIdx.x;
    const int w = tid >> 5, lane = tid & 31;
    const int g = lane >> 2, t = lane & 3;
    const int mi = lane >> 3, rr = lane & 7;
    const int q0 = qt * 128;
    const int r0 = 16 * w + g;
    const int q_g0 = q0 + r0, q_g1 = q_g0 + 8;

    // Q fragments (gmem direct; rows are warp-private), scaled by QSCALE via HMUL2
    const __half2 qsc = __float2half2_rn(QSCALE);
    uint32_t qa[4][4];
#pragma unroll
    for (int kk = 0; kk < 4; ++kk) {
        qa[kk][0] = *reinterpret_cast<const uint32_t*>(Qp + (size_t)q_g0 * DH_ + 16 * kk + 2 * t);
        qa[kk][1] = *reinterpret_cast<const uint32_t*>(Qp + (size_t)q_g1 * DH_ + 16 * kk + 2 * t);
        qa[kk][2] = *reinterpret_cast<const uint32_t*>(Qp + (size_t)q_g0 * DH_ + 16 * kk + 2 * t + 8);
        qa[kk][3] = *reinterpret_cast<const uint32_t*>(Qp + (size_t)q_g1 * DH_ + 16 * kk + 2 * t + 8);
#pragma unroll
        for (int r = 0; r < 4; ++r) {
            __half2 hq = *reinterpret_cast<__half2*>(&qa[kk][r]);
            hq = __hmul2(hq, qsc);
            qa[kk][r] = *reinterpret_cast<uint32_t*>(&hq);
        }
    }

    float z[8][4];
#pragma unroll
    for (int nt = 0; nt < 8; ++nt)
#pragma unroll
        for (int r = 0; r < 4; ++r) z[nt][r] = 0.f;
    float l0 = 0.f, l1 = 0.f;

    const int NC = 2 * qt + 2;   // always >= 2

    attn_prefetch(Kp, VTp, 0, K_st[0], V_st[0]); CP_COMMIT;
    attn_prefetch(Kp, VTp, 1, K_st[1], V_st[1]); CP_COMMIT;

#pragma unroll 1
    for (int kt = 0; kt < NC; ++kt) {
        CP_WAIT1;          // stage kt drained (per-thread)
        __syncthreads();   // publish stage kt; stage (kt+2)%3 free of readers
        if (kt + 2 < NC)
            attn_prefetch(Kp, VTp, kt + 2, K_st[(kt + 2) % 3], V_st[(kt + 2) % 3]);
        CP_COMMIT;

        const uint32_t kbase = smem_u32(K_st[kt % 3]);
        const uint32_t vbase = smem_u32(V_st[kt % 3]);

        // ---- S = Q @ K^T  (base-2 domain; scale folded into Q frags) ----
        float sv[8][4];
#pragma unroll
        for (int nt = 0; nt < 8; ++nt)
#pragma unroll
            for (int r = 0; r < 4; ++r) sv[nt][r] = 0.f;
#pragma unroll
        for (int kk = 0; kk < 4; ++kk) {
            uint32_t kb0[8], kb1[8];
#pragma unroll
            for (int j = 0; j < 4; ++j) {
                uint32_t addr = kbase + (uint32_t)(((16 * j + ((mi & 2) ? 8 : 0) + rr) * AKST + kk * 16 + ((mi & 1) ? 8 : 0)) * 2);
                ldsm_x4(kb0[2 * j], kb1[2 * j], kb0[2 * j + 1], kb1[2 * j + 1], addr);
            }
#pragma unroll
            for (int nt = 0; nt < 8; ++nt)
                mma_f16(sv[nt], qa[kk], kb0[nt], kb1[nt]);
        }

        // ---- causal mask on diagonal tiles ----
        if (kt >= 2 * qt) {
#pragma unroll
            for (int nt = 0; nt < 8; ++nt) {
                int p = kt * 64 + 8 * nt + 2 * t;
                if (p     > q_g0) sv[nt][0] = -1e30f;
                if (p + 1 > q_g0) sv[nt][1] = -1e30f;
                if (p     > q_g1) sv[nt][2] = -1e30f;
                if (p + 1 > q_g1) sv[nt][3] = -1e30f;
            }
        }

        // ---- P = 2^S via ex2.approx.f16x2 (straight into MMA A-regs) ----
        uint32_t ph0[8], ph1[8];
#pragma unroll
        for (int nt = 0; nt < 8; ++nt) {
            ph0[nt] = exp2_f16x2(sv[nt][0], sv[nt][1]);
            ph1[nt] = exp2_f16x2(sv[nt][2], sv[nt][3]);
        }

        // ---- Z += P @ V ----
#pragma unroll
        for (int kk2 = 0; kk2 < 4; ++kk2) {
            uint32_t pa[4] = {ph0[2 * kk2], ph1[2 * kk2], ph0[2 * kk2 + 1], ph1[2 * kk2 + 1]};
            uint32_t vb0[8], vb1[8];
#pragma unroll
            for (int j = 0; j < 4; ++j) {
                uint32_t addr = vbase + (uint32_t)(((16 * j + ((mi & 2) ? 8 : 0) + rr) * AKST + kk2 * 16 + ((mi & 1) ? 8 : 0)) * 2);
                ldsm_x4(vb0[2 * j], vb1[2 * j], vb0[2 * j + 1], vb1[2 * j + 1], addr);
            }
#pragma unroll
            for (int nt = 0; nt < 8; ++nt)
                mma_f16(z[nt], pa, vb0[nt], vb1[nt]);
        }

        // ---- denominator (HADD2 tree, off the MMA critical path) ----
        {
            __half2 la0 = __float2half2_rn(0.f), la1 = __float2half2_rn(0.f);
#pragma unroll
            for (int nt = 0; nt < 8; ++nt) {
                la0 = __hadd2(la0, *reinterpret_cast<__half2*>(&ph0[nt]));
                la1 = __hadd2(la1, *reinterpret_cast<__half2*>(&ph1[nt]));
            }
            float2 f0 = __half22float2(la0);
            float2 f1 = __half22float2(la1);
            l0 += f0.x + f0.y;
            l1 += f1.x + f1.y;
        }
    }

    // reduce denominators across the 4 t-lanes of each row group
#pragma unroll
    for (int o = 1; o < 4; o <<= 1) {
        l0 += __shfl_xor_sync(0xffffffffu, l0, o);
        l1 += __shfl_xor_sync(0xffffffffu, l1, o);
    }
    float inv0 = 1.f / (l0 + (float)(S_ - 1 - q_g0));
    float inv1 = 1.f / (l1 + (float)(S_ - 1 - q_g1));
    const float* suf0 = g_Suf + ((size_t)bh * S_ + q_g0) * DH_;
    const float* suf1 = g_Suf + ((size_t)bh * S_ + q_g1) * DH_;
    __half* zr0 = g_Zh + ((size_t)(b * S_ + q_g0) * H_ + h) * DH_;
    __half* zr1 = g_Zh + ((size_t)(b * S_ + q_g1) * H_ + h) * DH_;
#pragma unroll
    for (int nt = 0; nt < 8; ++nt) {
        int c = 8 * nt + 2 * t;
        float2 sA = *reinterpret_cast<const float2*>(suf0 + c);
        float2 sB = *reinterpret_cast<const float2*>(suf1 + c);
        *reinterpret_cast<__half2*>(zr0 + c) =
            __floats2half2_rn((z[nt][0] + sA.x) * inv0, (z[nt][1] + sA.y) * inv0);
        *reinterpret_cast<__half2*>(zr1 + c) =
            __floats2half2_rn((z[nt][2] + sB.x) * inv1, (z[nt][3] + sB.y) * inv1);
    }
}

// ---------------- kernel 6: LN2 on resid_mid (g_AO) + residual ----------------
__global__ void __launch_bounds__(256) final_kernel(
    const float* __restrict__ w, const float* __restrict__ b, float* __restrict__ out)
{
    __shared__ float sbuf[8];
    int row = blockIdx.x;
    float4 rm = reinterpret_cast<const float4*>(g_AO + (size_t)row * D_)[threadIdx.x];
    float s = rm.x + rm.y + rm.z + rm.w;
    float mean = block_reduce_sum(s, sbuf) * (1.f / D_);
    float4 c;
    c.x = rm.x - mean; c.y = rm.y - mean; c.z = rm.z - mean; c.w = rm.w - mean;
    float ss = c.x*c.x + c.y*c.y + c.z*c.z + c.w*c.w;
    float var = block_reduce_sum(ss, sbuf) * (1.f / D_);
    float inv = rsqrtf(var + 1e-5f);
    float4 wv = reinterpret_cast<const float4*>(w)[threadIdx.x];
    float4 bv = reinterpret_cast<const float4*>(b)[threadIdx.x];
    float4 o;
    o.x = rm.x + (c.x * inv * wv.x + bv.x);
    o.y = rm.y + (c.y * inv * wv.y + bv.y);
    o.z = rm.z + (c.z * inv * wv.z + bv.z);
    o.w = rm.w + (c.w * inv * wv.w + bv.w);
    reinterpret_cast<float4*>(out + (size_t)row * D_)[threadIdx.x] = o;
}

// ---------------- launch ----------------
extern "C" void kernel_launch(void* const* d_in, const int* in_sizes, int n_in,
                              void* d_out, int out_size)
{
    const float* resid = (const float*)d_in[0];
    const float* Wq    = (const float*)d_in[1];
    const float* bq    = (const float*)d_in[2];
    const float* Wk    = (const float*)d_in[3];
    const float* bk    = (const float*)d_in[4];
    const float* Wv    = (const float*)d_in[5];
    const float* bv    = (const float*)d_in[6];
    const float* Wo    = (const float*)d_in[7];
    const float* bo    = (const float*)d_in[8];
    const float* ln1w  = (const float*)d_in[9];
    const float* ln1b  = (const float*)d_in[10];
    const float* ln2w  = (const float*)d_in[11];
    const float* ln2b  = (const float*)d_in[12];
    float* out = (float*)d_out;

    cudaFuncSetAttribute(gemm_qkv_h,  cudaFuncAttributeMaxDynamicSharedMemorySize, GEMM_SMEM);
    cudaFuncSetAttribute(gemm_o_h,    cudaFuncAttributeMaxDynamicSharedMemorySize, GEMM_SMEM);
    cudaFuncSetAttribute(attn_kernel, cudaFuncAttributeMaxDynamicSharedMemorySize, ATTN_SMEM);

    prep_kernel<<<8192, 256>>>(Wq, Wk, Wv, Wo, resid, ln1w, ln1b);
    gemm_qkv_h<<<dim3(M_ / 128, 24), 256, GEMM_SMEM>>>(bq, bk, bv);
    suffix_kernel<<<B_ * H_, 1024>>>();
    attn_kernel<<<dim3(16, H_, B_), 256, ATTN_SMEM>>>();
    gemm_o_h<<<dim3(M_ / 128, 8), 256, GEMM_SMEM>>>(bo, resid);
    final_kernel<<<M_, 256>>>(ln2w, ln2b, out);
}

// round 16
// speedup vs baseline: 1.1339x; 1.1172x over previous
#include <cuda_runtime.h>
#include <cuda_fp16.h>
#include <stdint.h>
#include <math.h>

#define B_  2
#define S_  2048
#define D_  1024
#define H_  16
#define DH_ 64
#define M_  (B_ * S_)   // 4096

// softmax scale * log2(e): applied to Q fragments inside attention (base-2 softmax)
#define QSCALE 0.18033688011112042f

// ---------------- scratch (device globals; no allocation allowed) ----------------
__device__ __half g_Xh [M_ * D_];            // LN1 output fp16 [B*S, D]
__device__ __half g_Wh [3 * D_ * D_];        // K-major fused QKV weights fp16 [3072 n][1024 k]
__device__ __half g_WOh[D_ * D_];            // K-major O weights fp16 [1024 n][1024 k]
__device__ __half g_Qh [B_ * H_ * S_ * DH_]; // [B,H,S,Dh] fp16
__device__ __half g_Kh [B_ * H_ * S_ * DH_];
__device__ __half g_Vh [B_ * H_ * S_ * DH_];
__device__ __half g_VTh[B_ * H_ * DH_ * S_]; // V transposed [B,H,Dh,S] fp16
__device__ float  g_Suf[B_ * H_ * S_ * DH_]; // suffix sums of V (fp32)
__device__ __half g_Zh [M_ * D_];            // attn z fp16, [B,S,H*Dh]
__device__ float  g_AO [M_ * D_];            // resid_mid = resid + attn_out (fp32)

// ---------------- low-level helpers ----------------
__device__ __forceinline__ uint32_t smem_u32(const void* p) {
    return (uint32_t)__cvta_generic_to_shared(p);
}
__device__ __forceinline__ void mma_f16(float c[4], const uint32_t a[4], uint32_t b0, uint32_t b1) {
    asm volatile(
        "mma.sync.aligned.m16n8k16.row.col.f32.f16.f16.f32 "
        "{%0,%1,%2,%3}, {%4,%5,%6,%7}, {%8,%9}, {%0,%1,%2,%3};"
        : "+f"(c[0]), "+f"(c[1]), "+f"(c[2]), "+f"(c[3])
        : "r"(a[0]), "r"(a[1]), "r"(a[2]), "r"(a[3]), "r"(b0), "r"(b1));
}
__device__ __forceinline__ void ldsm_x4(uint32_t& r0, uint32_t& r1, uint32_t& r2, uint32_t& r3, uint32_t addr) {
    asm volatile("ldmatrix.sync.aligned.m8n8.x4.shared.b16 {%0,%1,%2,%3}, [%4];"
                 : "=r"(r0), "=r"(r1), "=r"(r2), "=r"(r3) : "r"(addr));
}
__device__ __forceinline__ void cp_async16(uint32_t saddr, const void* gaddr) {
    asm volatile("cp.async.cg.shared.global [%0], [%1], 16;" :: "r"(saddr), "l"(gaddr) : "memory");
}
#define CP_COMMIT asm volatile("cp.async.commit_group;" ::: "memory")
#define CP_WAIT1  asm volatile("cp.async.wait_group 1;" ::: "memory")

// pack two fp32 into f16x2 (lo = x, hi = y), then 2^x elementwise
__device__ __forceinline__ uint32_t exp2_f16x2(float x, float y) {
    uint32_t c;
    asm("cvt.rn.f16x2.f32 %0, %1, %2;" : "=r"(c) : "f"(y), "f"(x));  // hi=y, lo=x
    asm("ex2.approx.f16x2 %0, %1;" : "=r"(c) : "r"(c));
    return c;
}

// ---------------- block reduction ----------------
__device__ __forceinline__ float block_reduce_sum(float v, float* sbuf) {
    int lane = threadIdx.x & 31, wid = threadIdx.x >> 5;
#pragma unroll
    for (int o = 16; o > 0; o >>= 1) v += __shfl_xor_sync(0xffffffffu, v, o);
    if (lane == 0) sbuf[wid] = v;
    __syncthreads();
    if (wid == 0) {
        float t = (lane < 8) ? sbuf[lane] : 0.f;
#pragma unroll
        for (int o = 4; o > 0; o >>= 1) t += __shfl_xor_sync(0xffffffffu, t, o);
        if (lane == 0) sbuf[0] = t;
    }
    __syncthreads();
    float r = sbuf[0];
    __syncthreads();
    return r;
}

// ======= kernel 1 (fused prep): weight transposes + LN1, one launch =======
__global__ void __launch_bounds__(256) prep_kernel(
    const float* __restrict__ Wq, const float* __restrict__ Wk, const float* __restrict__ Wv,
    const float* __restrict__ WO,
    const float* __restrict__ in, const float* __restrict__ lw, const float* __restrict__ lb)
{
    __shared__ float tbuf[32][33];
    const int bid = blockIdx.x;
    const int tx = threadIdx.x & 31, ty = threadIdx.x >> 5;

    if (bid < 3072) {
        int z = bid >> 6, rem = bid & 63;
        int x = rem & 31, y = rem >> 5;
        int w = z >> 4, h = z & 15;
        const float* W = (w == 0) ? Wq : (w == 1) ? Wk : Wv;
        const float* src = W + (size_t)h * D_ * DH_;
        int d0 = x * 32, n0 = y * 32;
#pragma unroll
        for (int j = 0; j < 32; j += 8)
            tbuf[ty + j][tx] = src[(size_t)(d0 + ty + j) * DH_ + n0 + tx];
        __syncthreads();
        __half* dst = g_Wh + ((size_t)z * DH_ + n0) * D_ + d0;
#pragma unroll
        for (int j = 0; j < 32; j += 8)
            dst[(size_t)(ty + j) * D_ + tx] = __float2half_rn(tbuf[tx][ty + j]);
    } else if (bid < 4096) {
        int obid = bid - 3072;
        int x0 = (obid & 31) * 32, y0 = (obid >> 5) * 32;
#pragma unroll
        for (int j = 0; j < 32; j += 8)
            tbuf[ty + j][tx] = WO[(size_t)(x0 + ty + j) * D_ + y0 + tx];
        __syncthreads();
#pragma unroll
        for (int j = 0; j < 32; j += 8)
            g_WOh[(size_t)(y0 + ty + j) * D_ + x0 + tx] = __float2half_rn(tbuf[tx][ty + j]);
    } else {
        float* sbuf = &tbuf[0][0];
        int row = bid - 4096;
        float4 x = reinterpret_cast<const float4*>(in + (size_t)row * D_)[threadIdx.x];
        float s = x.x + x.y + x.z + x.w;
        float mean = block_reduce_sum(s, sbuf) * (1.f / D_);
        x.x -= mean; x.y -= mean; x.z -= mean; x.w -= mean;
        float ss = x.x*x.x + x.y*x.y + x.z*x.z + x.w*x.w;
        float var = block_reduce_sum(ss, sbuf) * (1.f / D_);
        float inv = rsqrtf(var + 1e-5f);
        float4 wv = reinterpret_cast<const float4*>(lw)[threadIdx.x];
        float4 bv = reinterpret_cast<const float4*>(lb)[threadIdx.x];
        __half2 h0 = __floats2half2_rn(x.x * inv * wv.x + bv.x, x.y * inv * wv.y + bv.y);
        __half2 h1 = __floats2half2_rn(x.z * inv * wv.z + bv.z, x.w * inv * wv.w + bv.w);
        uint2 pk;
        pk.x = *reinterpret_cast<uint32_t*>(&h0);
        pk.y = *reinterpret_cast<uint32_t*>(&h1);
        reinterpret_cast<uint2*>(g_Xh + (size_t)row * D_)[threadIdx.x] = pk;
    }
}

// ====== fp16 GEMM: CTA 128m x 128n, 256 thr, K-chunk 64, 3-stage ring, 1 sync/iter ======
#define GST 72    // smem row stride in halves (144 B)
#define GSTAGE_H (128 * GST)                  // halves per tensor per stage
#define GEMM_SMEM (3 * 2 * GSTAGE_H * 2)      // bytes: 3 stages x 2 tensors

__device__ __forceinline__ void gemm_prefetch64(
    const __half* __restrict__ gA, const __half* __restrict__ gB,
    int m0, int n0, int k0, __half* As, __half* Bs)
{
    const int tid = threadIdx.x;
#pragma unroll
    for (int i = 0; i < 4; ++i) {
        int idx = tid + i * 256;           // 0..1023
        int r = idx >> 3, c8 = (idx & 7) * 8;
        cp_async16(smem_u32(As + r * GST + c8), gA + (size_t)(m0 + r) * D_ + k0 + c8);
        cp_async16(smem_u32(Bs + r * GST + c8), gB + (size_t)(n0 + r) * D_ + k0 + c8);
    }
}

__device__ __forceinline__ void gemm_compute64(
    const __half* As, const __half* Bs, float acc[4][4][4], int wm, int wn, int lane)
{
    const uint32_t abase = smem_u32(As);
    const uint32_t bbase = smem_u32(Bs);
    const int mi = lane >> 3, rr = lane & 7;
#pragma unroll
    for (int kk = 0; kk < 4; ++kk) {
        uint32_t a[4][4];
#pragma unroll
        for (int mt = 0; mt < 4; ++mt) {
            uint32_t addr = abase + (uint32_t)(((wm * 64 + mt * 16 + (lane & 15)) * GST + kk * 16 + (lane >> 4) * 8) * 2);
            ldsm_x4(a[mt][0], a[mt][1], a[mt][2], a[mt][3], addr);
        }
        uint32_t b0[4], b1[4];
#pragma unroll
        for (int j = 0; j < 2; ++j) {
            uint32_t addr = bbase + (uint32_t)(((wn * 32 + 16 * j + ((mi & 2) ? 8 : 0) + rr) * GST + kk * 16 + ((mi & 1) ? 8 : 0)) * 2);
            ldsm_x4(b0[2 * j], b1[2 * j], b0[2 * j + 1], b1[2 * j + 1], addr);
        }
#pragma unroll
        for (int mt = 0; mt < 4; ++mt)
#pragma unroll
            for (int nt = 0; nt < 4; ++nt)
                mma_f16(acc[mt][nt], a[mt], b0[nt], b1[nt]);
    }
}

__device__ __forceinline__ void gemm16_main(
    const __half* __restrict__ gA, const __half* __restrict__ gB,
    int m0, int n0, __half* dynsm, float acc[4][4][4], int wm, int wn, int lane)
{
#pragma unroll
    for (int mt = 0; mt < 4; ++mt)
#pragma unroll
        for (int nt = 0; nt < 4; ++nt)
#pragma unroll
            for (int r = 0; r < 4; ++r) acc[mt][nt][r] = 0.f;

    __half* A_st[3] = {dynsm,                dynsm + 2 * GSTAGE_H, dynsm + 4 * GSTAGE_H};
    __half* B_st[3] = {dynsm + GSTAGE_H,     dynsm + 3 * GSTAGE_H, dynsm + 5 * GSTAGE_H};

    gemm_prefetch64(gA, gB, m0, n0, 0,  A_st[0], B_st[0]); CP_COMMIT;
    gemm_prefetch64(gA, gB, m0, n0, 64, A_st[1], B_st[1]); CP_COMMIT;

#pragma unroll 1
    for (int c = 0; c < 16; ++c) {
        CP_WAIT1;
        __syncthreads();
        if (c + 2 < 16)
            gemm_prefetch64(gA, gB, m0, n0, (c + 2) * 64, A_st[(c + 2) % 3], B_st[(c + 2) % 3]);
        CP_COMMIT;
        gemm_compute64(A_st[c % 3], B_st[c % 3], acc, wm, wn, lane);
    }
}

// QKV: grid (32 m-tiles, 24 n-tiles over fused N=3072)
__global__ void __launch_bounds__(256, 2) gemm_qkv_h(
    const float* __restrict__ bq, const float* __restrict__ bk, const float* __restrict__ bv)
{
    extern __shared__ __half dynsm[];
    const int m0 = blockIdx.x * 128, n0 = blockIdx.y * 128;
    const int tid = threadIdx.x, wid = tid >> 5, lane = tid & 31;
    const int wm = wid & 1, wn = wid >> 1;
    const int g = lane >> 2, t = lane & 3;

    float acc[4][4][4];
    gemm16_main(g_Xh, g_Wh, m0, n0, dynsm, acc, wm, wn, lane);

    const int wsel = n0 >> 10;
    __half* Out       = (wsel == 0) ? g_Qh : (wsel == 1) ? g_Kh : g_Vh;
    const float* bias = (wsel == 0) ? bq : (wsel == 1) ? bk : bv;

#pragma unroll
    for (int nt = 0; nt < 4; ++nt) {
        int cw = (n0 & 1023) + wn * 32 + nt * 8 + 2 * t;     // col within weight
        int h = cw >> 6, dh = cw & 63;
        float b0 = bias[cw], b1 = bias[cw + 1];
#pragma unroll
        for (int mt = 0; mt < 4; ++mt) {
#pragma unroll
            for (int hf = 0; hf < 2; ++hf) {
                int m = m0 + wm * 64 + mt * 16 + g + 8 * hf;
                int bb = m >> 11, ss = m & (S_ - 1);
                __half2 hv = __floats2half2_rn(acc[mt][nt][2 * hf] + b0, acc[mt][nt][2 * hf + 1] + b1);
                *reinterpret_cast<__half2*>(Out + ((size_t)((bb * H_ + h) * S_ + ss)) * DH_ + dh) = hv;
            }
        }
    }
}

// O-proj: grid (32, 8). Epilogue fuses resid add: g_AO = resid + attn_out (resid_mid).
__global__ void __launch_bounds__(256, 2) gemm_o_h(
    const float* __restrict__ bO, const float* __restrict__ resid)
{
    extern __shared__ __half dynsm[];
    const int m0 = blockIdx.x * 128, n0 = blockIdx.y * 128;
    const int tid = threadIdx.x, wid = tid >> 5, lane = tid & 31;
    const int wm = wid & 1, wn = wid >> 1;
    const int g = lane >> 2, t = lane & 3;

    float acc[4][4][4];
    gemm16_main(g_Zh, g_WOh, m0, n0, dynsm, acc, wm, wn, lane);

#pragma unroll
    for (int nt = 0; nt < 4; ++nt) {
        int col = n0 + wn * 32 + nt * 8 + 2 * t;
        float b0 = bO[col], b1 = bO[col + 1];
#pragma unroll
        for (int mt = 0; mt < 4; ++mt) {
#pragma unroll
            for (int hf = 0; hf < 2; ++hf) {
                int m = m0 + wm * 64 + mt * 16 + g + 8 * hf;
                float2 rp = *reinterpret_cast<const float2*>(resid + (size_t)m * D_ + col);
                float2 o;
                o.x = acc[mt][nt][2 * hf] + b0 + rp.x;
                o.y = acc[mt][nt][2 * hf + 1] + b1 + rp.y;
                *reinterpret_cast<float2*>(g_AO + (size_t)m * D_ + col) = o;
            }
        }
    }
}

// ---------------- kernel 3: suffix sums of V + V^T production ----------------
__global__ void __launch_bounds__(1024) suffix_kernel()
{
    int bh = blockIdx.x;
    int d  = threadIdx.x & 63;
    int seg = threadIdx.x >> 6;  // 0..15
    const __half* v = g_Vh + (size_t)bh * S_ * DH_;
    float* suf = g_Suf + (size_t)bh * S_ * DH_;
    __half* vtrow = g_VTh + ((size_t)bh * DH_ + d) * S_;

    int s_begin = seg * 128, s_end = s_begin + 128;
    float ssum = 0.f;
    for (int s = s_begin; s < s_end; ++s) ssum += __half2float(v[s * DH_ + d]);

    __shared__ float segsum[16][64];
    segsum[seg][d] = ssum;
    __syncthreads();
    float acc = 0.f;
    for (int tt = seg + 1; tt < 16; ++tt) acc += segsum[tt][d];

    for (int s0 = s_end - 8; s0 >= s_begin; s0 -= 8) {
        __half hv[8];
        float vv[8];
#pragma unroll
        for (int tt = 0; tt < 8; ++tt) {
            hv[tt] = v[(s0 + tt) * DH_ + d];
            vv[tt] = __half2float(hv[tt]);
        }
        *reinterpret_cast<uint4*>(vtrow + s0) = *reinterpret_cast<uint4*>(hv);
#pragma unroll
        for (int tt = 7; tt >= 0; --tt) { suf[(s0 + tt) * DH_ + d] = acc; acc += vv[tt]; }
    }
}

// ------ kernel 4: flash attention (fp16 MMA, base-2 softmax, 128-col stages) ------
// 1-D grid, strictly heavy-first: bid -> qt = 15 - bid/32, bh = bid%32.
// Stage = 128 K-cols as two 64-col sub-tiles (layout/compute identical to before);
// 3-stage ring halves the barrier count (one sync per 128 cols).
#define AKST 72                               // sub-tile row stride in halves (144 B)
#define ASUB_H (64 * AKST)                    // halves per 64-col sub-tile
#define ASTAGE_H (4 * ASUB_H)                 // K0,K1,V0,V1 per stage
#define ATTN_SMEM (3 * ASTAGE_H * 2)          // bytes = 110592 -> 2 CTAs/SM

__device__ __forceinline__ void attn_prefetch128(
    const __half* __restrict__ Kp, const __half* __restrict__ VTp,
    int kt2, __half* stage)
{
    const int tid = threadIdx.x;
    __half* K0 = stage;
    __half* K1 = stage + ASUB_H;
    __half* V0 = stage + 2 * ASUB_H;
    __half* V1 = stage + 3 * ASUB_H;
#pragma unroll
    for (int i = 0; i < 2; ++i) {
        int idx = tid + i * 256;
        int r = idx >> 3, c8 = (idx & 7) * 8;
        // K rows kt2*128 + {0..63} and {64..127}
        cp_async16(smem_u32(K0 + r * AKST + c8), Kp + (size_t)(kt2 * 128 + r) * DH_ + c8);
        cp_async16(smem_u32(K1 + r * AKST + c8), Kp + (size_t)(kt2 * 128 + 64 + r) * DH_ + c8);
        // V^T rows d=0..63, cols kt2*128 + {0..63} and {64..127}
        cp_async16(smem_u32(V0 + r * AKST + c8), VTp + (size_t)r * S_ + kt2 * 128 + c8);
        cp_async16(smem_u32(V1 + r * AKST + c8), VTp + (size_t)r * S_ + kt2 * 128 + 64 + c8);
    }
}

__global__ void __launch_bounds__(256, 2) attn_kernel()
{
    extern __shared__ __half asm_[];
    __half* stg[3] = {asm_, asm_ + ASTAGE_H, asm_ + 2 * ASTAGE_H};

    const int bid = blockIdx.x;
    const int qt = 15 - (bid >> 5);    // strictly heavy-first across the 1-D grid
    const int bh = bid & 31;
    const int b = bh >> 4, h = bh & 15;
    const __half* Qp  = g_Qh  + (size_t)bh * S_ * DH_;
    const __half* Kp  = g_Kh  + (size_t)bh * S_ * DH_;
    const __half* VTp = g_VTh + (size_t)bh * DH_ * S_;

    const int tid = threadIdx.x;
    const int w = tid >> 5, lane = tid & 31;
    const int g = lane >> 2, t = lane & 3;
    const int mi = lane >> 3, rr = lane & 7;
    const int q0 = qt * 128;
    const int r0 = 16 * w + g;
    const int q_g0 = q0 + r0, q_g1 = q_g0 + 8;

    // Q fragments (gmem direct; rows are warp-private), scaled by QSCALE via HMUL2
    const __half2 qsc = __float2half2_rn(QSCALE);
    uint32_t qa[4][4];
#pragma unroll
    for (int kk = 0; kk < 4; ++kk) {
        qa[kk][0] = *reinterpret_cast<const uint32_t*>(Qp + (size_t)q_g0 * DH_ + 16 * kk + 2 * t);
        qa[kk][1] = *reinterpret_cast<const uint32_t*>(Qp + (size_t)q_g1 * DH_ + 16 * kk + 2 * t);
        qa[kk][2] = *reinterpret_cast<const uint32_t*>(Qp + (size_t)q_g0 * DH_ + 16 * kk + 2 * t + 8);
        qa[kk][3] = *reinterpret_cast<const uint32_t*>(Qp + (size_t)q_g1 * DH_ + 16 * kk + 2 * t + 8);
#pragma unroll
        for (int r = 0; r < 4; ++r) {
            __half2 hq = *reinterpret_cast<__half2*>(&qa[kk][r]);
            hq = __hmul2(hq, qsc);
            qa[kk][r] = *reinterpret_cast<uint32_t*>(&hq);
        }
    }

    float z[8][4];
#pragma unroll
    for (int nt = 0; nt < 8; ++nt)
#pragma unroll
        for (int r = 0; r < 4; ++r) z[nt][r] = 0.f;
    float l0 = 0.f, l1 = 0.f;

    const int NC2 = qt + 1;   // 128-col stages; NC=2qt+2 is even

    attn_prefetch128(Kp, VTp, 0, stg[0]); CP_COMMIT;
    if (NC2 > 1) attn_prefetch128(Kp, VTp, 1, stg[1]);
    CP_COMMIT;

#pragma unroll 1
    for (int it = 0; it < NC2; ++it) {
        CP_WAIT1;          // stage it drained (per-thread)
        __syncthreads();   // publish stage it; stage (it+2)%3 free of readers
        if (it + 2 < NC2)
            attn_prefetch128(Kp, VTp, it + 2, stg[(it + 2) % 3]);
        CP_COMMIT;

        __half* stage = stg[it % 3];

#pragma unroll
        for (int sub = 0; sub < 2; ++sub) {
            const int kt = 2 * it + sub;
            const uint32_t kbase = smem_u32(stage + sub * ASUB_H);
            const uint32_t vbase = smem_u32(stage + (2 + sub) * ASUB_H);

            // ---- S = Q @ K^T  (base-2 domain) ----
            float sv[8][4];
#pragma unroll
            for (int nt = 0; nt < 8; ++nt)
#pragma unroll
                for (int r = 0; r < 4; ++r) sv[nt][r] = 0.f;
#pragma unroll
            for (int kk = 0; kk < 4; ++kk) {
                uint32_t kb0[8], kb1[8];
#pragma unroll
                for (int j = 0; j < 4; ++j) {
                    uint32_t addr = kbase + (uint32_t)(((16 * j + ((mi & 2) ? 8 : 0) + rr) * AKST + kk * 16 + ((mi & 1) ? 8 : 0)) * 2);
                    ldsm_x4(kb0[2 * j], kb1[2 * j], kb0[2 * j + 1], kb1[2 * j + 1], addr);
                }
#pragma unroll
                for (int nt = 0; nt < 8; ++nt)
                    mma_f16(sv[nt], qa[kk], kb0[nt], kb1[nt]);
            }

            // ---- causal mask on diagonal tiles (only last stage can hit) ----
            if (kt >= 2 * qt) {
#pragma unroll
                for (int nt = 0; nt < 8; ++nt) {
                    int p = kt * 64 + 8 * nt + 2 * t;
                    if (p     > q_g0) sv[nt][0] = -1e30f;
                    if (p + 1 > q_g0) sv[nt][1] = -1e30f;
                    if (p     > q_g1) sv[nt][2] = -1e30f;
                    if (p + 1 > q_g1) sv[nt][3] = -1e30f;
                }
            }

            // ---- P = 2^S via ex2.approx.f16x2 (straight into MMA A-regs) ----
            uint32_t ph0[8], ph1[8];
#pragma unroll
            for (int nt = 0; nt < 8; ++nt) {
                ph0[nt] = exp2_f16x2(sv[nt][0], sv[nt][1]);
                ph1[nt] = exp2_f16x2(sv[nt][2], sv[nt][3]);
            }

            // ---- Z += P @ V ----
#pragma unroll
            for (int kk2 = 0; kk2 < 4; ++kk2) {
                uint32_t pa[4] = {ph0[2 * kk2], ph1[2 * kk2], ph0[2 * kk2 + 1], ph1[2 * kk2 + 1]};
                uint32_t vb0[8], vb1[8];
#pragma unroll
                for (int j = 0; j < 4; ++j) {
                    uint32_t addr = vbase + (uint32_t)(((16 * j + ((mi & 2) ? 8 : 0) + rr) * AKST + kk2 * 16 + ((mi & 1) ? 8 : 0)) * 2);
                    ldsm_x4(vb0[2 * j], vb1[2 * j], vb0[2 * j + 1], vb1[2 * j + 1], addr);
                }
#pragma unroll
                for (int nt = 0; nt < 8; ++nt)
                    mma_f16(z[nt], pa, vb0[nt], vb1[nt]);
            }

            // ---- denominator (HADD2 tree, off the MMA critical path) ----
            {
                __half2 la0 = __float2half2_rn(0.f), la1 = __float2half2_rn(0.f);
#pragma unroll
                for (int nt = 0; nt < 8; ++nt) {
                    la0 = __hadd2(la0, *reinterpret_cast<__half2*>(&ph0[nt]));
                    la1 = __hadd2(la1, *reinterpret_cast<__half2*>(&ph1[nt]));
                }
                float2 f0 = __half22float2(la0);
                float2 f1 = __half22float2(la1);
                l0 += f0.x + f0.y;
                l1 += f1.x + f1.y;
            }
        }
    }

    // reduce denominators across the 4 t-lanes of each row group
#pragma unroll
    for (int o = 1; o < 4; o <<= 1) {
        l0 += __shfl_xor_sync(0xffffffffu, l0, o);
        l1 += __shfl_xor_sync(0xffffffffu, l1, o);
    }
    float inv0 = 1.f / (l0 + (float)(S_ - 1 - q_g0));
    float inv1 = 1.f / (l1 + (float)(S_ - 1 - q_g1));
    const float* suf0 = g_Suf + ((size_t)bh * S_ + q_g0) * DH_;
    const float* suf1 = g_Suf + ((size_t)bh * S_ + q_g1) * DH_;
    __half* zr0 = g_Zh + ((size_t)(b * S_ + q_g0) * H_ + h) * DH_;
    __half* zr1 = g_Zh + ((size_t)(b * S_ + q_g1) * H_ + h) * DH_;
#pragma unroll
    for (int nt = 0; nt < 8; ++nt) {
        int c = 8 * nt + 2 * t;
        float2 sA = *reinterpret_cast<const float2*>(suf0 + c);
        float2 sB = *reinterpret_cast<const float2*>(suf1 + c);
        *reinterpret_cast<__half2*>(zr0 + c) =
            __floats2half2_rn((z[nt][0] + sA.x) * inv0, (z[nt][1] + sA.y) * inv0);
        *reinterpret_cast<__half2*>(zr1 + c) =
            __floats2half2_rn((z[nt][2] + sB.x) * inv1, (z[nt][3] + sB.y) * inv1);
    }
}

// ---------------- kernel 6: LN2 on resid_mid (g_AO) + residual ----------------
__global__ void __launch_bounds__(256) final_kernel(
    const float* __restrict__ w, const float* __restrict__ b, float* __restrict__ out)
{
    __shared__ float sbuf[8];
    int row = blockIdx.x;
    float4 rm = reinterpret_cast<const float4*>(g_AO + (size_t)row * D_)[threadIdx.x];
    float s = rm.x + rm.y + rm.z + rm.w;
    float mean = block_reduce_sum(s, sbuf) * (1.f / D_);
    float4 c;
    c.x = rm.x - mean; c.y = rm.y - mean; c.z = rm.z - mean; c.w = rm.w - mean;
    float ss = c.x*c.x + c.y*c.y + c.z*c.z + c.w*c.w;
    float var = block_reduce_sum(ss, sbuf) * (1.f / D_);
    float inv = rsqrtf(var + 1e-5f);
    float4 wv = reinterpret_cast<const float4*>(w)[threadIdx.x];
    float4 bv = reinterpret_cast<const float4*>(b)[threadIdx.x];
    float4 o;
    o.x = rm.x + (c.x * inv * wv.x + bv.x);
    o.y = rm.y + (c.y * inv * wv.y + bv.y);
    o.z = rm.z + (c.z * inv * wv.z + bv.z);
    o.w = rm.w + (c.w * inv * wv.w + bv.w);
    reinterpret_cast<float4*>(out + (size_t)row * D_)[threadIdx.x] = o;
}

// ---------------- launch ----------------
extern "C" void kernel_launch(void* const* d_in, const int* in_sizes, int n_in,
                              void* d_out, int out_size)
{
    const float* resid = (const float*)d_in[0];
    const float* Wq    = (const float*)d_in[1];
    const float* bq    = (const float*)d_in[2];
    const float* Wk    = (const float*)d_in[3];
    const float* bk    = (const float*)d_in[4];
    const float* Wv    = (const float*)d_in[5];
    const float* bv    = (const float*)d_in[6];
    const float* Wo    = (const float*)d_in[7];
    const float* bo    = (const float*)d_in[8];
    const float* ln1w  = (const float*)d_in[9];
    const float* ln1b  = (const float*)d_in[10];
    const float* ln2w  = (const float*)d_in[11];
    const float* ln2b  = (const float*)d_in[12];
    float* out = (float*)d_out;

    cudaFuncSetAttribute(gemm_qkv_h,  cudaFuncAttributeMaxDynamicSharedMemorySize, GEMM_SMEM);
    cudaFuncSetAttribute(gemm_o_h,    cudaFuncAttributeMaxDynamicSharedMemorySize, GEMM_SMEM);
    cudaFuncSetAttribute(attn_kernel, cudaFuncAttributeMaxDynamicSharedMemorySize, ATTN_SMEM);

    prep_kernel<<<8192, 256>>>(Wq, Wk, Wv, Wo, resid, ln1w, ln1b);
    gemm_qkv_h<<<dim3(M_ / 128, 24), 256, GEMM_SMEM>>>(bq, bk, bv);
    suffix_kernel<<<B_ * H_, 1024>>>();
    attn_kernel<<<512, 256, ATTN_SMEM>>>();
    gemm_o_h<<<dim3(M_ / 128, 8), 256, GEMM_SMEM>>>(bo, resid);
    final_kernel<<<M_, 256>>>(ln2w, ln2b, out);
}